// round 6
// baseline (speedup 1.0000x reference)
#include <cuda_runtime.h>
#include <cuda_fp16.h>
#include <stdint.h>

#define SPLITK 148
#define KCHUNK 32
#define LTOT   256
#define DDIM   128
#define HDIM   64

// scratch (allocation-free rule: __device__ globals)
__device__ float g_part[SPLITK * LTOT * DDIM];      // split-K partial numerators
__device__ float g_zpart[SPLITK * LTOT];            // split-K partial denominators

// ---------------------------------------------------------------------------
// helpers
// ---------------------------------------------------------------------------
__device__ __forceinline__ void ldsm_x4(uint32_t* r, uint32_t addr) {
    asm volatile("ldmatrix.sync.aligned.m8n8.x4.shared.b16 {%0,%1,%2,%3}, [%4];"
        : "=r"(r[0]), "=r"(r[1]), "=r"(r[2]), "=r"(r[3]) : "r"(addr));
}
__device__ __forceinline__ void ldsm_x4_t(uint32_t* r, uint32_t addr) {
    asm volatile("ldmatrix.sync.aligned.m8n8.x4.trans.shared.b16 {%0,%1,%2,%3}, [%4];"
        : "=r"(r[0]), "=r"(r[1]), "=r"(r[2]), "=r"(r[3]) : "r"(addr));
}
__device__ __forceinline__ void mma_fp16(float* c, const uint32_t* a, uint32_t b0, uint32_t b1) {
    asm volatile("mma.sync.aligned.m16n8k16.row.col.f32.f16.f16.f32 "
        "{%0,%1,%2,%3}, {%4,%5,%6,%7}, {%8,%9}, {%0,%1,%2,%3};"
        : "+f"(c[0]), "+f"(c[1]), "+f"(c[2]), "+f"(c[3])
        : "r"(a[0]), "r"(a[1]), "r"(a[2]), "r"(a[3]), "r"(b0), "r"(b1));
}
__device__ __forceinline__ uint2 pack_half4(float x, float y, float z, float w) {
    __half2 lo = __floats2half2_rn(x, y);
    __half2 hi = __floats2half2_rn(z, w);
    uint2 v;
    v.x = *(uint32_t*)&lo;
    v.y = *(uint32_t*)&hi;
    return v;
}

// ---------------------------------------------------------------------------
// Fused kernel: per CTA (one split y of the K dimension, ALL 256 l):
//   per 32-token chunk:
//     feats fp32 -> fp16 smem (B operand, reused by MLP)
//     warps 12-15: h = tanh(f@W1+b1); raw logits = h@W2 (MMA, overlapped)
//     p = exp(raw + b2) (32 lanes)
//     mp = mask * p -> fp16 A operand; Z += mp (fp32, fused)
//     big MMA: num[l,d] += mp[l,k] * f16[k,d]
// grid = 148 CTAs x 512 thr (one wave). 3 syncs/chunk, LDGs one phase ahead.
// ---------------------------------------------------------------------------
#define MA_STR 40    // 32 k + 8 pad (halves)
#define G_STR  136   // 128 d + 8 pad (halves)
#define W1_STR 72    // 64 j + 8 pad (halves)
#define MA_HALVES (LTOT*MA_STR)     // 10240
#define G_HALVES  (KCHUNK*G_STR)    // 4352
#define SM2_BYTES ((2*MA_HALVES + 2*G_HALVES + 128*W1_STR)*2 + (LTOT*8 + 64 + 32)*4)

__global__ __launch_bounds__(512, 1) void k2_fused(
    const float* __restrict__ feats, const float* __restrict__ mask,
    const float* __restrict__ W1, const float* __restrict__ b1,
    const float* __restrict__ W2, const float* __restrict__ b2,
    int B, int chunksPerSplit)
{
    extern __shared__ char smraw[];
    __half* mA   = (__half*)smraw;                   // 2 x [256 l][40]
    __half* fS   = mA + 2*MA_HALVES;                 // 2 x [32 k][136]
    __half* wS   = fS + 2*G_HALVES;                  // [128 d][72]
    float*  zsm  = (float*)(wS + 128*W1_STR);        // [256][8]
    float*  praw = zsm + LTOT*8;                     // [64] (two j-halves)
    float*  pfin = praw + 64;                        // [32]

    int tid  = threadIdx.x;
    int y    = blockIdx.x;
    int wid  = tid >> 5, lane = tid & 31;
    int wm   = wid & 7, wn = wid >> 3;

    uint32_t mA_s = (uint32_t)__cvta_generic_to_shared(mA);
    uint32_t fS_s = (uint32_t)__cvta_generic_to_shared(fS);
    uint32_t wS_s = (uint32_t)__cvta_generic_to_shared(wS);

    float acc[2][8][4];
    #pragma unroll
    for (int mt = 0; mt < 2; mt++)
        #pragma unroll
        for (int nt = 0; nt < 8; nt++)
            #pragma unroll
            for (int e = 0; e < 4; e++) acc[mt][nt][e] = 0.f;
    float zacc[4] = {0.f, 0.f, 0.f, 0.f};

    // staging maps
    int mrow = tid >> 3, mc4 = tid & 7;      // mask: l rows mrow+64i, k-col mc4*4
    // feats: idx = tid + i*512 -> frow = idx>>5 (token), fc4 = idx&31 (d/4)

    float4 m4[4];   // mask(c) during staging; loaded one phase ahead
    float4 f4[2];   // feats(c+1) fp32, loaded one phase ahead

    int kb0 = y * chunksPerSplit * KCHUNK;

    // ---- prologue ----
    // stage W1 -> wS fp16
    #pragma unroll
    for (int i = 0; i < 4; i++) {
        int idx = tid + i*512;
        int row = idx >> 4, c4 = idx & 15;
        float4 v = ((const float4*)W1)[idx];
        *(uint2*)(wS + row*W1_STR + c4*4) = pack_half4(v.x, v.y, v.z, v.w);
    }
    // stage feats(0) -> fS[0]
    #pragma unroll
    for (int i = 0; i < 2; i++) {
        int idx = tid + i*512;
        int frow = idx >> 5, fc4 = idx & 31;
        int tok = kb0 + frow;
        float4 v = (tok < B) ? ((const float4*)(feats + (size_t)tok*DDIM))[fc4]
                             : make_float4(0.f, 0.f, 0.f, 0.f);
        *(uint2*)(fS + frow*G_STR + fc4*4) = pack_half4(v.x, v.y, v.z, v.w);
    }
    // prefetch mask(0), feats(1)
    {
        int gk = kb0 + mc4*4;
        #pragma unroll
        for (int i = 0; i < 4; i++)
            m4[i] = (gk < B) ? *((const float4*)(mask + (size_t)(mrow + i*64)*B + gk))
                             : make_float4(0.f, 0.f, 0.f, 0.f);
        #pragma unroll
        for (int i = 0; i < 2; i++) {
            int idx = tid + i*512;
            int tok = kb0 + KCHUNK + (idx >> 5);
            f4[i] = (tok < B && chunksPerSplit > 1)
                  ? ((const float4*)(feats + (size_t)tok*DDIM))[idx & 31]
                  : make_float4(0.f, 0.f, 0.f, 0.f);
        }
    }
    __syncthreads();

    // MLP(0): warps 12-15 on fS[0]
    if (wid >= 12) {
        int w = wid - 12;
        int trow0 = (w & 1) * 16;
        int jh = w >> 1;
        float a1[4][4];
        #pragma unroll
        for (int q = 0; q < 4; q++)
            #pragma unroll
            for (int e = 0; e < 4; e++) a1[q][e] = 0.f;
        #pragma unroll
        for (int ks = 0; ks < 8; ks++) {
            uint32_t a[4];
            ldsm_x4(a, fS_s + (uint32_t)(((trow0 + (lane & 15))*G_STR
                              + ks*16 + ((lane >> 4) << 3)) * 2));
            #pragma unroll
            for (int nq = 0; nq < 2; nq++) {
                uint32_t b[4];
                ldsm_x4_t(b, wS_s + (uint32_t)(((ks*16 + (lane & 15))*W1_STR
                                  + jh*32 + nq*16 + ((lane >> 4) << 3)) * 2));
                mma_fp16(a1[nq*2],     a, b[0], b[1]);
                mma_fp16(a1[nq*2 + 1], a, b[2], b[3]);
            }
        }
        float p0 = 0.f, p1 = 0.f;
        #pragma unroll
        for (int nb = 0; nb < 4; nb++) {
            int j0 = jh*32 + nb*8 + (lane & 3)*2;
            float b1a = __ldg(b1 + j0), b1b = __ldg(b1 + j0 + 1);
            float w2a = __ldg(W2 + j0), w2b = __ldg(W2 + j0 + 1);
            p0 += tanhf(a1[nb][0] + b1a)*w2a + tanhf(a1[nb][1] + b1b)*w2b;
            p1 += tanhf(a1[nb][2] + b1a)*w2a + tanhf(a1[nb][3] + b1b)*w2b;
        }
        p0 += __shfl_xor_sync(0xffffffffu, p0, 1);
        p0 += __shfl_xor_sync(0xffffffffu, p0, 2);
        p1 += __shfl_xor_sync(0xffffffffu, p1, 1);
        p1 += __shfl_xor_sync(0xffffffffu, p1, 2);
        if ((lane & 3) == 0) {
            int t = trow0 + (lane >> 2);
            praw[jh*32 + t]     = p0;
            praw[jh*32 + t + 8] = p1;
        }
    }

    // ---- main loop ----
    for (int c = 0; c < chunksPerSplit; c++) {
        __syncthreads();                       // praw(c) visible
        if (tid < 32)
            pfin[tid] = expf(praw[tid] + praw[32 + tid] + __ldg(b2));
        __syncthreads();                       // pfin visible

        // stage mp(c) = mask*p -> mA[c&1]; Z fused
        {
            float4 p4 = *(float4*)(pfin + mc4*4);
            __half* mA_c = mA + (c & 1) * MA_HALVES;
            #pragma unroll
            for (int i = 0; i < 4; i++) {
                float4 v = m4[i];
                float mpx = v.x*p4.x, mpy = v.y*p4.y, mpz = v.z*p4.z, mpw = v.w*p4.w;
                zacc[i] += mpx + mpy + mpz + mpw;
                *(uint2*)(mA_c + (mrow + i*64)*MA_STR + mc4*4) = pack_half4(mpx, mpy, mpz, mpw);
            }
        }
        // stage feats(c+1) -> fS[(c+1)&1]
        if (c + 1 < chunksPerSplit) {
            __half* fS_n = fS + ((c + 1) & 1) * G_HALVES;
            #pragma unroll
            for (int i = 0; i < 2; i++) {
                int idx = tid + i*512;
                *(uint2*)(fS_n + (idx >> 5)*G_STR + (idx & 31)*4)
                    = pack_half4(f4[i].x, f4[i].y, f4[i].z, f4[i].w);
            }
        }
        __syncthreads();                       // mA[c&1], fS[(c+1)&1] visible

        // issue next-phase LDGs: mask(c+1), feats(c+2)
        if (c + 1 < chunksPerSplit) {
            int gk = kb0 + (c + 1)*KCHUNK + mc4*4;
            #pragma unroll
            for (int i = 0; i < 4; i++)
                m4[i] = (gk < B) ? *((const float4*)(mask + (size_t)(mrow + i*64)*B + gk))
                                 : make_float4(0.f, 0.f, 0.f, 0.f);
        }
        if (c + 2 < chunksPerSplit) {
            #pragma unroll
            for (int i = 0; i < 2; i++) {
                int idx = tid + i*512;
                int tok = kb0 + (c + 2)*KCHUNK + (idx >> 5);
                f4[i] = (tok < B) ? ((const float4*)(feats + (size_t)tok*DDIM))[idx & 31]
                                  : make_float4(0.f, 0.f, 0.f, 0.f);
            }
        }

        // MLP(c+1) on fS[(c+1)&1] (warps 12-15), overlapped with big MMA
        if (wid >= 12 && c + 1 < chunksPerSplit) {
            int w = wid - 12;
            int trow0 = (w & 1) * 16;
            int jh = w >> 1;
            uint32_t fS_b = fS_s + (uint32_t)((((c + 1) & 1) * G_HALVES) * 2);
            float a1[4][4];
            #pragma unroll
            for (int q = 0; q < 4; q++)
                #pragma unroll
                for (int e = 0; e < 4; e++) a1[q][e] = 0.f;
            #pragma unroll
            for (int ks = 0; ks < 8; ks++) {
                uint32_t a[4];
                ldsm_x4(a, fS_b + (uint32_t)(((trow0 + (lane & 15))*G_STR
                                  + ks*16 + ((lane >> 4) << 3)) * 2));
                #pragma unroll
                for (int nq = 0; nq < 2; nq++) {
                    uint32_t b[4];
                    ldsm_x4_t(b, wS_s + (uint32_t)(((ks*16 + (lane & 15))*W1_STR
                                      + jh*32 + nq*16 + ((lane >> 4) << 3)) * 2));
                    mma_fp16(a1[nq*2],     a, b[0], b[1]);
                    mma_fp16(a1[nq*2 + 1], a, b[2], b[3]);
                }
            }
            float p0 = 0.f, p1 = 0.f;
            #pragma unroll
            for (int nb = 0; nb < 4; nb++) {
                int j0 = jh*32 + nb*8 + (lane & 3)*2;
                float b1a = __ldg(b1 + j0), b1b = __ldg(b1 + j0 + 1);
                float w2a = __ldg(W2 + j0), w2b = __ldg(W2 + j0 + 1);
                p0 += tanhf(a1[nb][0] + b1a)*w2a + tanhf(a1[nb][1] + b1b)*w2b;
                p1 += tanhf(a1[nb][2] + b1a)*w2a + tanhf(a1[nb][3] + b1b)*w2b;
            }
            p0 += __shfl_xor_sync(0xffffffffu, p0, 1);
            p0 += __shfl_xor_sync(0xffffffffu, p0, 2);
            p1 += __shfl_xor_sync(0xffffffffu, p1, 1);
            p1 += __shfl_xor_sync(0xffffffffu, p1, 2);
            if ((lane & 3) == 0) {
                int t = trow0 + (lane >> 2);
                praw[jh*32 + t]     = p0;
                praw[jh*32 + t + 8] = p1;
            }
        }

        // big MMA(c): mA[c&1] x fS[c&1]
        uint32_t mA_b = mA_s + (uint32_t)((c & 1) * MA_HALVES * 2);
        uint32_t fS_b = fS_s + (uint32_t)((c & 1) * G_HALVES * 2);
        #pragma unroll
        for (int ks = 0; ks < 2; ks++) {
            uint32_t a[2][4];
            #pragma unroll
            for (int mt = 0; mt < 2; mt++)
                ldsm_x4(a[mt], mA_b + (uint32_t)(((wm*32 + mt*16 + (lane & 15)) * MA_STR
                                 + ks*16 + ((lane >> 4) << 3)) * 2));
            #pragma unroll
            for (int np = 0; np < 4; np++) {
                uint32_t b[4];
                ldsm_x4_t(b, fS_b + (uint32_t)(((ks*16 + (lane & 15)) * G_STR
                                 + wn*64 + np*16 + ((lane >> 4) << 3)) * 2));
                #pragma unroll
                for (int mt = 0; mt < 2; mt++) {
                    mma_fp16(acc[mt][np*2],     a[mt], b[0], b[1]);
                    mma_fp16(acc[mt][np*2 + 1], a[mt], b[2], b[3]);
                }
            }
        }
    }

    // ---- deterministic Z reduction ----
    __syncthreads();
    #pragma unroll
    for (int i = 0; i < 4; i++)
        zsm[(mrow + i*64)*8 + mc4] = zacc[i];
    __syncthreads();
    if (tid < LTOT) {
        float z = 0.f;
        #pragma unroll
        for (int j = 0; j < 8; j++) z += zsm[tid*8 + j];
        g_zpart[y*LTOT + tid] = z;
    }

    // ---- write numerator partials ----
    #pragma unroll
    for (int mt = 0; mt < 2; mt++) {
        #pragma unroll
        for (int nt = 0; nt < 8; nt++) {
            int grow = wm*32 + mt*16 + (lane >> 2);
            int gcol = wn*64 + nt*8 + (lane & 3)*2;
            size_t b0 = ((size_t)y*LTOT + grow) * DDIM + gcol;
            size_t b1o = ((size_t)y*LTOT + grow + 8) * DDIM + gcol;
            *(float2*)(g_part + b0)  = make_float2(acc[mt][nt][0], acc[mt][nt][1]);
            *(float2*)(g_part + b1o) = make_float2(acc[mt][nt][2], acc[mt][nt][3]);
        }
    }
}

// ---------------------------------------------------------------------------
// Kernel 3: reduce split-K partials, divide by Z, zero empty libraries
// ---------------------------------------------------------------------------
__global__ void k3_reduce(float* __restrict__ out)
{
    int l = blockIdx.x, d = threadIdx.x;
    float num = 0.f, z = 0.f;
    #pragma unroll 4
    for (int y = 0; y < SPLITK; y++) {
        num += g_part[((size_t)y*LTOT + l) * DDIM + d];
        z   += g_zpart[y*LTOT + l];
    }
    out[l*DDIM + d] = (z > 0.f) ? num / z : 0.f;
}

// ---------------------------------------------------------------------------
extern "C" void kernel_launch(void* const* d_in, const int* in_sizes, int n_in,
                              void* d_out, int out_size)
{
    const float* feats = (const float*)d_in[0];
    const float* mask  = (const float*)d_in[1];
    const float* W1    = (const float*)d_in[2];
    const float* b1    = (const float*)d_in[3];
    const float* W2    = (const float*)d_in[4];
    const float* b2    = (const float*)d_in[5];
    float* out = (float*)d_out;

    int B = in_sizes[0] / DDIM;           // 200000
    int totalChunks = (B + KCHUNK - 1) / KCHUNK;
    int cps = (totalChunks + SPLITK - 1) / SPLITK;

    cudaFuncSetAttribute(k2_fused, cudaFuncAttributeMaxDynamicSharedMemorySize, SM2_BYTES);

    k2_fused<<<SPLITK, 512, SM2_BYTES>>>(feats, mask, W1, b1, W2, b2, B, cps);

    k3_reduce<<<LTOT, DDIM>>>(out);
}

// round 7
// speedup vs baseline: 1.2465x; 1.2465x over previous
#include <cuda_runtime.h>
#include <cuda_fp16.h>
#include <stdint.h>

#define SPLITK 148
#define KCHUNK 32
#define LTOT   256
#define DDIM   128

// scratch (allocation-free rule: __device__ globals)
__device__ float g_p[200064];                       // exp(logits) per token
__device__ float g_part[SPLITK * LTOT * DDIM];      // split-K partial numerators
__device__ float g_zpart[SPLITK * LTOT];            // split-K partial denominators

// ---------------------------------------------------------------------------
// helpers
// ---------------------------------------------------------------------------
__device__ __forceinline__ void ldsm_x4(uint32_t* r, uint32_t addr) {
    asm volatile("ldmatrix.sync.aligned.m8n8.x4.shared.b16 {%0,%1,%2,%3}, [%4];"
        : "=r"(r[0]), "=r"(r[1]), "=r"(r[2]), "=r"(r[3]) : "r"(addr));
}
__device__ __forceinline__ void ldsm_x4_t(uint32_t* r, uint32_t addr) {
    asm volatile("ldmatrix.sync.aligned.m8n8.x4.trans.shared.b16 {%0,%1,%2,%3}, [%4];"
        : "=r"(r[0]), "=r"(r[1]), "=r"(r[2]), "=r"(r[3]) : "r"(addr));
}
__device__ __forceinline__ void mma_fp16(float* c, const uint32_t* a, uint32_t b0, uint32_t b1) {
    asm volatile("mma.sync.aligned.m16n8k16.row.col.f32.f16.f16.f32 "
        "{%0,%1,%2,%3}, {%4,%5,%6,%7}, {%8,%9}, {%0,%1,%2,%3};"
        : "+f"(c[0]), "+f"(c[1]), "+f"(c[2]), "+f"(c[3])
        : "r"(a[0]), "r"(a[1]), "r"(a[2]), "r"(a[3]), "r"(b0), "r"(b1));
}
__device__ __forceinline__ uint2 pack_half4(float x, float y, float z, float w) {
    __half2 lo = __floats2half2_rn(x, y);
    __half2 hi = __floats2half2_rn(z, w);
    uint2 v;
    v.x = *(uint32_t*)&lo;
    v.y = *(uint32_t*)&hi;
    return v;
}

// ---------------------------------------------------------------------------
// Kernel 1: p = exp(W2 . tanh(f @ W1 + b1) + b2), fp16 MMA (round-4 version).
// tile = 128 tokens, full K=128 staged once. warp = 16 tok x 64 j.
// ---------------------------------------------------------------------------
#define A1_STR 136
#define W1_STR 72
#define SM1_BYTES ((128*A1_STR + 128*W1_STR) * 2)

__global__ __launch_bounds__(256, 2) void k1_logits(
    const float* __restrict__ feats, const float* __restrict__ W1,
    const float* __restrict__ b1, const float* __restrict__ W2,
    const float* __restrict__ b2, int B)
{
    extern __shared__ __half sm1[];
    __half* aS = sm1;                  // [128 tok][136]
    __half* wS = sm1 + 128*A1_STR;     // [128 k][72]

    int tid = threadIdx.x;
    int tok0 = blockIdx.x * 128;
    int wid = tid >> 5, lane = tid & 31;

    #pragma unroll
    for (int i = 0; i < 16; i++) {
        int idx = tid + i*256;
        int row = idx >> 5, c4 = idx & 31;
        int tok = tok0 + row;
        float4 v = make_float4(0.f, 0.f, 0.f, 0.f);
        if (tok < B) v = ((const float4*)(feats + (size_t)tok*DDIM))[c4];
        *(uint2*)(aS + row*A1_STR + c4*4) = pack_half4(v.x, v.y, v.z, v.w);
    }
    #pragma unroll
    for (int i = 0; i < 8; i++) {
        int idx = tid + i*256;
        int row = idx >> 4, c4 = idx & 15;
        float4 v = ((const float4*)W1)[idx];
        *(uint2*)(wS + row*W1_STR + c4*4) = pack_half4(v.x, v.y, v.z, v.w);
    }
    __syncthreads();

    uint32_t aS_s = (uint32_t)__cvta_generic_to_shared(aS);
    uint32_t wS_s = (uint32_t)__cvta_generic_to_shared(wS);

    float acc[8][4];
    #pragma unroll
    for (int nt = 0; nt < 8; nt++)
        #pragma unroll
        for (int e = 0; e < 4; e++) acc[nt][e] = 0.f;

    #pragma unroll
    for (int ks = 0; ks < 8; ks++) {
        uint32_t a[4];
        ldsm_x4(a, aS_s + (uint32_t)(((wid*16 + (lane & 15)) * A1_STR
                          + ks*16 + ((lane >> 4) << 3)) * 2));
        #pragma unroll
        for (int np = 0; np < 4; np++) {
            uint32_t b[4];
            ldsm_x4_t(b, wS_s + (uint32_t)(((ks*16 + (lane & 15)) * W1_STR
                              + np*16 + ((lane >> 4) << 3)) * 2));
            mma_fp16(acc[np*2],     a, b[0], b[1]);
            mma_fp16(acc[np*2 + 1], a, b[2], b[3]);
        }
    }

    float s0 = 0.f, s1 = 0.f;
    #pragma unroll
    for (int nt = 0; nt < 8; nt++) {
        int j0 = nt*8 + (lane & 3)*2;
        float b1a = __ldg(b1 + j0), b1b = __ldg(b1 + j0 + 1);
        float w2a = __ldg(W2 + j0), w2b = __ldg(W2 + j0 + 1);
        s0 += tanhf(acc[nt][0] + b1a) * w2a + tanhf(acc[nt][1] + b1b) * w2b;
        s1 += tanhf(acc[nt][2] + b1a) * w2a + tanhf(acc[nt][3] + b1b) * w2b;
    }
    #pragma unroll
    for (int m = 1; m <= 2; m <<= 1) {
        s0 += __shfl_xor_sync(0xffffffffu, s0, m);
        s1 += __shfl_xor_sync(0xffffffffu, s1, m);
    }
    if ((lane & 3) == 0) {
        float bb2 = __ldg(b2);
        int r = lane >> 2;
        int tok = tok0 + wid*16 + r;
        if (tok < B)     g_p[tok]     = expf(s0 + bb2);
        if (tok + 8 < B) g_p[tok + 8] = expf(s1 + bb2);
    }
}

// ---------------------------------------------------------------------------
// Kernel 2: split-K fp16 MMA, num[l,d] = sum_b (mask[l,b]*p[b]) * f16(f[b,d]).
// One 512-thread CTA per split covers ALL 256 l (feats fp32 read ONCE).
// Register prefetch for mask+feats+p, double-buffered smem, 1 sync/chunk.
// grid = 148 (one wave), 16 warps: wm = wid&7 (32 l), wn = wid>>3 (64 d).
// ---------------------------------------------------------------------------
#define MA_STR 40    // 32 k + 8 pad (halves)
#define G_STR  136   // 128 d + 8 pad (halves)
#define MA_HALVES (LTOT*MA_STR)   // 10240
#define G_HALVES  (KCHUNK*G_STR)  // 4352
#define SM2_BYTES ((2*MA_HALVES + 2*G_HALVES) * 2 + LTOT*8*4)

__global__ __launch_bounds__(512, 1) void k2_mma(
    const float* __restrict__ feats, const float* __restrict__ mask,
    int B, int chunksPerSplit)
{
    extern __shared__ char smraw[];
    __half* mA  = (__half*)smraw;                    // 2 x [256 l][40]
    __half* fS  = mA + 2*MA_HALVES;                  // 2 x [32 k][136]
    float*  zsm = (float*)(fS + 2*G_HALVES);         // [256][8]

    int tid  = threadIdx.x;
    int y    = blockIdx.x;
    int wid  = tid >> 5, lane = tid & 31;
    int wm   = wid & 7, wn = wid >> 3;

    float acc[2][8][4];
    #pragma unroll
    for (int mt = 0; mt < 2; mt++)
        #pragma unroll
        for (int nt = 0; nt < 8; nt++)
            #pragma unroll
            for (int e = 0; e < 4; e++) acc[mt][nt][e] = 0.f;
    float zacc[4] = {0.f, 0.f, 0.f, 0.f};

    uint32_t mA_s = (uint32_t)__cvta_generic_to_shared(mA);
    uint32_t fS_s = (uint32_t)__cvta_generic_to_shared(fS);

    // staging maps
    int mrow = tid >> 3, mc4 = tid & 7;      // mask: l rows mrow+64i, k-col mc4*4
    // feats: idx = tid + i*512 -> token idx>>5, d-col (idx&31)*4

    float4 m4[4], f4[2], p4;
    int kb0 = y * chunksPerSplit * KCHUNK;

    // prologue: chunk 0 regs
    {
        int gk = kb0 + mc4*4;
        p4 = (gk < B) ? *((const float4*)(g_p + gk)) : make_float4(0.f,0.f,0.f,0.f);
        #pragma unroll
        for (int i = 0; i < 4; i++)
            m4[i] = (gk < B) ? *((const float4*)(mask + (size_t)(mrow + i*64)*B + gk))
                             : make_float4(0.f, 0.f, 0.f, 0.f);
        #pragma unroll
        for (int i = 0; i < 2; i++) {
            int idx = tid + i*512;
            int tok = kb0 + (idx >> 5);
            f4[i] = (tok < B) ? ((const float4*)(feats + (size_t)tok*DDIM))[idx & 31]
                              : make_float4(0.f, 0.f, 0.f, 0.f);
        }
    }

    for (int c = 0; c < chunksPerSplit; c++) {
        __half* mA_c = mA + (c & 1) * MA_HALVES;
        __half* fS_c = fS + (c & 1) * G_HALVES;

        // stage mp(c) = mask*p -> fp16; Z fused
        #pragma unroll
        for (int i = 0; i < 4; i++) {
            float4 v = m4[i];
            float mpx = v.x*p4.x, mpy = v.y*p4.y, mpz = v.z*p4.z, mpw = v.w*p4.w;
            zacc[i] += mpx + mpy + mpz + mpw;
            *(uint2*)(mA_c + (mrow + i*64)*MA_STR + mc4*4) = pack_half4(mpx, mpy, mpz, mpw);
        }
        // stage feats(c) fp32 regs -> fp16
        #pragma unroll
        for (int i = 0; i < 2; i++) {
            int idx = tid + i*512;
            *(uint2*)(fS_c + (idx >> 5)*G_STR + (idx & 31)*4)
                = pack_half4(f4[i].x, f4[i].y, f4[i].z, f4[i].w);
        }

        // prefetch chunk c+1 regs
        if (c + 1 < chunksPerSplit) {
            int kb2 = kb0 + (c + 1)*KCHUNK;
            int gk = kb2 + mc4*4;
            p4 = (gk < B) ? *((const float4*)(g_p + gk)) : make_float4(0.f,0.f,0.f,0.f);
            #pragma unroll
            for (int i = 0; i < 4; i++)
                m4[i] = (gk < B) ? *((const float4*)(mask + (size_t)(mrow + i*64)*B + gk))
                                 : make_float4(0.f, 0.f, 0.f, 0.f);
            #pragma unroll
            for (int i = 0; i < 2; i++) {
                int idx = tid + i*512;
                int tok = kb2 + (idx >> 5);
                f4[i] = (tok < B) ? ((const float4*)(feats + (size_t)tok*DDIM))[idx & 31]
                                  : make_float4(0.f, 0.f, 0.f, 0.f);
            }
        }
        __syncthreads();   // staged buffers visible; MMA(c-1) done

        // MMA over chunk c
        uint32_t mA_b = mA_s + (uint32_t)((c & 1) * MA_HALVES * 2);
        uint32_t fS_b = fS_s + (uint32_t)((c & 1) * G_HALVES * 2);
        #pragma unroll
        for (int ks = 0; ks < 2; ks++) {
            uint32_t a[2][4];
            #pragma unroll
            for (int mt = 0; mt < 2; mt++)
                ldsm_x4(a[mt], mA_b + (uint32_t)(((wm*32 + mt*16 + (lane & 15)) * MA_STR
                                 + ks*16 + ((lane >> 4) << 3)) * 2));
            #pragma unroll
            for (int np = 0; np < 4; np++) {
                uint32_t b[4];
                ldsm_x4_t(b, fS_b + (uint32_t)(((ks*16 + (lane & 15)) * G_STR
                                 + wn*64 + np*16 + ((lane >> 4) << 3)) * 2));
                #pragma unroll
                for (int mt = 0; mt < 2; mt++) {
                    mma_fp16(acc[mt][np*2],     a[mt], b[0], b[1]);
                    mma_fp16(acc[mt][np*2 + 1], a[mt], b[2], b[3]);
                }
            }
        }
    }

    // deterministic Z reduction
    __syncthreads();
    #pragma unroll
    for (int i = 0; i < 4; i++)
        zsm[(mrow + i*64)*8 + mc4] = zacc[i];
    __syncthreads();
    if (tid < LTOT) {
        float z = 0.f;
        #pragma unroll
        for (int j = 0; j < 8; j++) z += zsm[tid*8 + j];
        g_zpart[y*LTOT + tid] = z;
    }

    // write numerator partials
    #pragma unroll
    for (int mt = 0; mt < 2; mt++) {
        #pragma unroll
        for (int nt = 0; nt < 8; nt++) {
            int grow = wm*32 + mt*16 + (lane >> 2);
            int gcol = wn*64 + nt*8 + (lane & 3)*2;
            size_t b0 = ((size_t)y*LTOT + grow) * DDIM + gcol;
            size_t b1 = ((size_t)y*LTOT + grow + 8) * DDIM + gcol;
            *(float2*)(g_part + b0) = make_float2(acc[mt][nt][0], acc[mt][nt][1]);
            *(float2*)(g_part + b1) = make_float2(acc[mt][nt][2], acc[mt][nt][3]);
        }
    }
}

// ---------------------------------------------------------------------------
// Kernel 3: parallel reduce of split-K partials, divide by Z, zero empties.
// 256 blocks x 512 thr; 4 y-groups of 37 per block; smem combine.
// ---------------------------------------------------------------------------
__global__ __launch_bounds__(512, 2) void k3_reduce(float* __restrict__ out)
{
    __shared__ float nsm[4][DDIM];
    __shared__ float zsm4[4];

    int l = blockIdx.x;
    int tid = threadIdx.x;
    int g = tid >> 7;         // y-group 0..3
    int d = tid & 127;

    int y0 = g * 37, y1 = y0 + 37;   // 4*37 = 148 = SPLITK
    float num = 0.f, z = 0.f;
    #pragma unroll 4
    for (int y = y0; y < y1; y++) {
        num += g_part[((size_t)y*LTOT + l) * DDIM + d];
        z   += g_zpart[y*LTOT + l];
    }
    nsm[g][d] = num;
    if (d == 0) zsm4[g] = z;
    __syncthreads();

    if (g == 0) {
        float n = nsm[0][d] + nsm[1][d] + nsm[2][d] + nsm[3][d];
        float zz = zsm4[0] + zsm4[1] + zsm4[2] + zsm4[3];
        out[l*DDIM + d] = (zz > 0.f) ? n / zz : 0.f;
    }
}

// ---------------------------------------------------------------------------
extern "C" void kernel_launch(void* const* d_in, const int* in_sizes, int n_in,
                              void* d_out, int out_size)
{
    const float* feats = (const float*)d_in[0];
    const float* mask  = (const float*)d_in[1];
    const float* W1    = (const float*)d_in[2];
    const float* b1    = (const float*)d_in[3];
    const float* W2    = (const float*)d_in[4];
    const float* b2    = (const float*)d_in[5];
    float* out = (float*)d_out;

    int B = in_sizes[0] / DDIM;           // 200000
    int totalChunks = (B + KCHUNK - 1) / KCHUNK;
    int cps = (totalChunks + SPLITK - 1) / SPLITK;

    cudaFuncSetAttribute(k1_logits, cudaFuncAttributeMaxDynamicSharedMemorySize, SM1_BYTES);
    cudaFuncSetAttribute(k2_mma,    cudaFuncAttributeMaxDynamicSharedMemorySize, SM2_BYTES);

    int g1 = (B + 127) / 128;
    k1_logits<<<g1, 256, SM1_BYTES>>>(feats, W1, b1, W2, b2, B);

    k2_mma<<<SPLITK, 512, SM2_BYTES>>>(feats, mask, B, cps);

    k3_reduce<<<LTOT, 512>>>(out);
}

// round 8
// speedup vs baseline: 1.2498x; 1.0026x over previous
#include <cuda_runtime.h>
#include <cuda_fp16.h>
#include <stdint.h>

#define SPLITK 148
#define KCHUNK 32
#define LTOT   256
#define DDIM   128

// scratch (allocation-free rule: __device__ globals)
__device__ float g_part[SPLITK * LTOT * DDIM];      // split-K partial numerators
__device__ float g_zpart[SPLITK * LTOT];            // split-K partial denominators

// ---------------------------------------------------------------------------
// helpers
// ---------------------------------------------------------------------------
__device__ __forceinline__ void ldsm_x4(uint32_t* r, uint32_t addr) {
    asm volatile("ldmatrix.sync.aligned.m8n8.x4.shared.b16 {%0,%1,%2,%3}, [%4];"
        : "=r"(r[0]), "=r"(r[1]), "=r"(r[2]), "=r"(r[3]) : "r"(addr));
}
__device__ __forceinline__ void ldsm_x4_t(uint32_t* r, uint32_t addr) {
    asm volatile("ldmatrix.sync.aligned.m8n8.x4.trans.shared.b16 {%0,%1,%2,%3}, [%4];"
        : "=r"(r[0]), "=r"(r[1]), "=r"(r[2]), "=r"(r[3]) : "r"(addr));
}
__device__ __forceinline__ void mma_fp16(float* c, const uint32_t* a, uint32_t b0, uint32_t b1) {
    asm volatile("mma.sync.aligned.m16n8k16.row.col.f32.f16.f16.f32 "
        "{%0,%1,%2,%3}, {%4,%5,%6,%7}, {%8,%9}, {%0,%1,%2,%3};"
        : "+f"(c[0]), "+f"(c[1]), "+f"(c[2]), "+f"(c[3])
        : "r"(a[0]), "r"(a[1]), "r"(a[2]), "r"(a[3]), "r"(b0), "r"(b1));
}
__device__ __forceinline__ uint2 pack_half4(float x, float y, float z, float w) {
    __half2 lo = __floats2half2_rn(x, y);
    __half2 hi = __floats2half2_rn(z, w);
    uint2 v;
    v.x = *(uint32_t*)&lo;
    v.y = *(uint32_t*)&hi;
    return v;
}

// ---------------------------------------------------------------------------
// Fused kernel. Per CTA = one K-split y, all 256 l. Per 32-token chunk:
//   A) MLP(c): all 16 warps, warp w = 16 tok (w&1) x 8 j (w>>1), full k=128,
//      8 HMMA -> tanh -> dot W2 -> praw[jg][tok]
//   B) sync
//   C) warp0: pfin = exp(sum_j praw + b2); all: stage fS(c+1); LDG f(c+2)
//   D) sync
//   E) stage mp(c) = mask*pfin -> mA fp16 (Z fused); LDG mask(c+1)
//   F) sync
//   G) big MMA(c): 256l x 128d x 32k, warp = 32 l x 64 d
// grid = 148 x 512 (one wave, 1 CTA/SM).
// ---------------------------------------------------------------------------
#define MA_STR 40    // 32 k + 8 pad (halves)
#define G_STR  136   // 128 d + 8 pad (halves)
#define W1_STR 72    // 64 j + 8 pad (halves)
#define MA_HALVES (LTOT*MA_STR)     // 10240 (single buffer)
#define G_HALVES  (KCHUNK*G_STR)    // 4352
#define SM2_BYTES ((MA_HALVES + 2*G_HALVES + 128*W1_STR)*2 + (LTOT*8 + 8*32 + 32)*4)

__global__ __launch_bounds__(512, 1) void k2_fused(
    const float* __restrict__ feats, const float* __restrict__ mask,
    const float* __restrict__ W1, const float* __restrict__ b1,
    const float* __restrict__ W2, const float* __restrict__ b2,
    int B, int chunksPerSplit)
{
    extern __shared__ char smraw[];
    __half* mA   = (__half*)smraw;                   // [256 l][40]
    __half* fS   = mA + MA_HALVES;                   // 2 x [32 tok][136]
    __half* wS   = fS + 2*G_HALVES;                  // [128 d][72]
    float*  zsm  = (float*)(wS + 128*W1_STR);        // [256][8]
    float*  praw = zsm + LTOT*8;                     // [8 jg][32 tok]
    float*  pfin = praw + 8*32;                      // [32]

    int tid  = threadIdx.x;
    int y    = blockIdx.x;
    int wid  = tid >> 5, lane = tid & 31;
    int wm   = wid & 7, wn = wid >> 3;       // big MMA mapping
    int tokg = wid & 1, jg = wid >> 1;       // MLP mapping

    uint32_t mA_s = (uint32_t)__cvta_generic_to_shared(mA);
    uint32_t fS_s = (uint32_t)__cvta_generic_to_shared(fS);
    uint32_t wS_s = (uint32_t)__cvta_generic_to_shared(wS);

    float acc[2][8][4];
    #pragma unroll
    for (int mt = 0; mt < 2; mt++)
        #pragma unroll
        for (int nt = 0; nt < 8; nt++)
            #pragma unroll
            for (int e = 0; e < 4; e++) acc[mt][nt][e] = 0.f;
    float zacc[4] = {0.f, 0.f, 0.f, 0.f};

    // per-warp MLP constants (j0 fixed across chunks)
    int j0 = jg*8 + (lane & 3)*2;
    float b1a = __ldg(b1 + j0), b1b = __ldg(b1 + j0 + 1);
    float w2a = __ldg(W2 + j0), w2b = __ldg(W2 + j0 + 1);
    float b2v = __ldg(b2);

    // staging maps
    int mrow = tid >> 3, mc4 = tid & 7;      // mask: l rows mrow+64i, k-col mc4*4

    float4 m4[4], f4[2];
    int kb0 = y * chunksPerSplit * KCHUNK;

    // ---- prologue ----
    #pragma unroll
    for (int i = 0; i < 4; i++) {            // W1 -> wS fp16
        int idx = tid + i*512;
        int row = idx >> 4, c4 = idx & 15;
        float4 v = ((const float4*)W1)[idx];
        *(uint2*)(wS + row*W1_STR + c4*4) = pack_half4(v.x, v.y, v.z, v.w);
    }
    #pragma unroll
    for (int i = 0; i < 2; i++) {            // feats(0) -> fS[0]
        int idx = tid + i*512;
        int tok = kb0 + (idx >> 5);
        float4 v = (tok < B) ? ((const float4*)(feats + (size_t)tok*DDIM))[idx & 31]
                             : make_float4(0.f, 0.f, 0.f, 0.f);
        *(uint2*)(fS + (idx >> 5)*G_STR + (idx & 31)*4) = pack_half4(v.x, v.y, v.z, v.w);
    }
    {   // prefetch mask(0), feats(1)
        int gk = kb0 + mc4*4;
        #pragma unroll
        for (int i = 0; i < 4; i++)
            m4[i] = (gk < B) ? *((const float4*)(mask + (size_t)(mrow + i*64)*B + gk))
                             : make_float4(0.f, 0.f, 0.f, 0.f);
        #pragma unroll
        for (int i = 0; i < 2; i++) {
            int idx = tid + i*512;
            int tok = kb0 + KCHUNK + (idx >> 5);
            f4[i] = (tok < B && chunksPerSplit > 1)
                  ? ((const float4*)(feats + (size_t)tok*DDIM))[idx & 31]
                  : make_float4(0.f, 0.f, 0.f, 0.f);
        }
    }
    __syncthreads();

    // ---- main loop ----
    for (int c = 0; c < chunksPerSplit; c++) {
        uint32_t fS_b = fS_s + (uint32_t)((c & 1) * G_HALVES * 2);

        // A) MLP(c): 8 HMMA over k=128, output 16 tok x 8 j per warp
        {
            float mc[4] = {0.f, 0.f, 0.f, 0.f};
            #pragma unroll
            for (int ks = 0; ks < 8; ks++) {
                uint32_t a[4];
                ldsm_x4(a, fS_b + (uint32_t)(((tokg*16 + (lane & 15))*G_STR
                                  + ks*16 + ((lane >> 4) << 3)) * 2));
                uint32_t b[4];
                ldsm_x4_t(b, wS_s + (uint32_t)(((ks*16 + (lane & 15))*W1_STR
                                  + jg*8 + ((lane >> 4) << 3)) * 2));
                mma_fp16(mc, a, b[0], b[1]);
            }
            float s0 = tanhf(mc[0] + b1a)*w2a + tanhf(mc[1] + b1b)*w2b;
            float s1 = tanhf(mc[2] + b1a)*w2a + tanhf(mc[3] + b1b)*w2b;
            s0 += __shfl_xor_sync(0xffffffffu, s0, 1);
            s0 += __shfl_xor_sync(0xffffffffu, s0, 2);
            s1 += __shfl_xor_sync(0xffffffffu, s1, 1);
            s1 += __shfl_xor_sync(0xffffffffu, s1, 2);
            if ((lane & 3) == 0) {
                int t = tokg*16 + (lane >> 2);
                praw[jg*32 + t]     = s0;
                praw[jg*32 + t + 8] = s1;
            }
        }
        __syncthreads();   // B) praw visible; MMA(c-1) done

        // C) pfin; stage fS(c+1); issue feats(c+2) LDGs
        if (tid < 32) {
            float s = b2v;
            #pragma unroll
            for (int g = 0; g < 8; g++) s += praw[g*32 + tid];
            pfin[tid] = expf(s);
        }
        if (c + 1 < chunksPerSplit) {
            __half* fS_n = fS + ((c + 1) & 1) * G_HALVES;
            #pragma unroll
            for (int i = 0; i < 2; i++) {
                int idx = tid + i*512;
                *(uint2*)(fS_n + (idx >> 5)*G_STR + (idx & 31)*4)
                    = pack_half4(f4[i].x, f4[i].y, f4[i].z, f4[i].w);
            }
        }
        if (c + 2 < chunksPerSplit) {
            #pragma unroll
            for (int i = 0; i < 2; i++) {
                int idx = tid + i*512;
                int tok = kb0 + (c + 2)*KCHUNK + (idx >> 5);
                f4[i] = (tok < B) ? ((const float4*)(feats + (size_t)tok*DDIM))[idx & 31]
                                  : make_float4(0.f, 0.f, 0.f, 0.f);
            }
        }
        __syncthreads();   // D) pfin + fS(c+1) visible

        // E) stage mp(c) = mask * pfin -> mA; Z fused; then mask(c+1) LDGs
        {
            float4 p4 = *(float4*)(pfin + mc4*4);
            #pragma unroll
            for (int i = 0; i < 4; i++) {
                float4 v = m4[i];
                float mpx = v.x*p4.x, mpy = v.y*p4.y, mpz = v.z*p4.z, mpw = v.w*p4.w;
                zacc[i] += mpx + mpy + mpz + mpw;
                *(uint2*)(mA + (mrow + i*64)*MA_STR + mc4*4) = pack_half4(mpx, mpy, mpz, mpw);
            }
        }
        if (c + 1 < chunksPerSplit) {
            int gk = kb0 + (c + 1)*KCHUNK + mc4*4;
            #pragma unroll
            for (int i = 0; i < 4; i++)
                m4[i] = (gk < B) ? *((const float4*)(mask + (size_t)(mrow + i*64)*B + gk))
                                 : make_float4(0.f, 0.f, 0.f, 0.f);
        }
        __syncthreads();   // F) mA visible

        // G) big MMA(c)
        #pragma unroll
        for (int ks = 0; ks < 2; ks++) {
            uint32_t a[2][4];
            #pragma unroll
            for (int mt = 0; mt < 2; mt++)
                ldsm_x4(a[mt], mA_s + (uint32_t)(((wm*32 + mt*16 + (lane & 15)) * MA_STR
                                 + ks*16 + ((lane >> 4) << 3)) * 2));
            #pragma unroll
            for (int np = 0; np < 4; np++) {
                uint32_t b[4];
                ldsm_x4_t(b, fS_b + (uint32_t)(((ks*16 + (lane & 15)) * G_STR
                                 + wn*64 + np*16 + ((lane >> 4) << 3)) * 2));
                #pragma unroll
                for (int mt = 0; mt < 2; mt++) {
                    mma_fp16(acc[mt][np*2],     a[mt], b[0], b[1]);
                    mma_fp16(acc[mt][np*2 + 1], a[mt], b[2], b[3]);
                }
            }
        }
    }

    // ---- deterministic Z reduction ----
    __syncthreads();
    #pragma unroll
    for (int i = 0; i < 4; i++)
        zsm[(mrow + i*64)*8 + mc4] = zacc[i];
    __syncthreads();
    if (tid < LTOT) {
        float z = 0.f;
        #pragma unroll
        for (int j = 0; j < 8; j++) z += zsm[tid*8 + j];
        g_zpart[y*LTOT + tid] = z;
    }

    // ---- write numerator partials ----
    #pragma unroll
    for (int mt = 0; mt < 2; mt++) {
        #pragma unroll
        for (int nt = 0; nt < 8; nt++) {
            int grow = wm*32 + mt*16 + (lane >> 2);
            int gcol = wn*64 + nt*8 + (lane & 3)*2;
            size_t o0 = ((size_t)y*LTOT + grow) * DDIM + gcol;
            size_t o1 = ((size_t)y*LTOT + grow + 8) * DDIM + gcol;
            *(float2*)(g_part + o0) = make_float2(acc[mt][nt][0], acc[mt][nt][1]);
            *(float2*)(g_part + o1) = make_float2(acc[mt][nt][2], acc[mt][nt][3]);
        }
    }
}

// ---------------------------------------------------------------------------
// Kernel 3: parallel reduce of split-K partials, divide by Z, zero empties.
// ---------------------------------------------------------------------------
__global__ __launch_bounds__(512, 2) void k3_reduce(float* __restrict__ out)
{
    __shared__ float nsm[4][DDIM];
    __shared__ float zsm4[4];

    int l = blockIdx.x;
    int tid = threadIdx.x;
    int g = tid >> 7;
    int d = tid & 127;

    int y0 = g * 37, y1 = y0 + 37;   // 4*37 = 148
    float num = 0.f, z = 0.f;
    #pragma unroll 4
    for (int y = y0; y < y1; y++) {
        num += g_part[((size_t)y*LTOT + l) * DDIM + d];
        z   += g_zpart[y*LTOT + l];
    }
    nsm[g][d] = num;
    if (d == 0) zsm4[g] = z;
    __syncthreads();

    if (g == 0) {
        float n = nsm[0][d] + nsm[1][d] + nsm[2][d] + nsm[3][d];
        float zz = zsm4[0] + zsm4[1] + zsm4[2] + zsm4[3];
        out[l*DDIM + d] = (zz > 0.f) ? n / zz : 0.f;
    }
}

// ---------------------------------------------------------------------------
extern "C" void kernel_launch(void* const* d_in, const int* in_sizes, int n_in,
                              void* d_out, int out_size)
{
    const float* feats = (const float*)d_in[0];
    const float* mask  = (const float*)d_in[1];
    const float* W1    = (const float*)d_in[2];
    const float* b1    = (const float*)d_in[3];
    const float* W2    = (const float*)d_in[4];
    const float* b2    = (const float*)d_in[5];
    float* out = (float*)d_out;

    int B = in_sizes[0] / DDIM;           // 200000
    int totalChunks = (B + KCHUNK - 1) / KCHUNK;
    int cps = (totalChunks + SPLITK - 1) / SPLITK;

    cudaFuncSetAttribute(k2_fused, cudaFuncAttributeMaxDynamicSharedMemorySize, SM2_BYTES);

    k2_fused<<<SPLITK, 512, SM2_BYTES>>>(feats, mask, W1, b1, W2, b2, B, cps);

    k3_reduce<<<LTOT, 512>>>(out);
}